// round 16
// baseline (speedup 1.0000x reference)
#include <cuda_runtime.h>
#include <cuda_bf16.h>
#include <math.h>
#include <stdint.h>

#define NNODES 100000
#define NEDGES 1600000
#define FDIN   256
#define FH     256
#define FOUT   64

typedef __nv_bfloat16 bf16;

// ---------------- scratch (device globals; no runtime allocation) ----------------
__device__ float g_buf0[(size_t)NNODES * 256];
__device__ float g_buf1[(size_t)NNODES * 256];
__device__ float g_buf2[(size_t)NNODES * 256];

__device__ bf16 g_xhi[(size_t)NNODES * 256];
__device__ bf16 g_xlo[(size_t)NNODES * 256];
__device__ bf16 g_zhi[(size_t)NNODES * 256];
__device__ bf16 g_zlo[(size_t)NNODES * 256];
__device__ bf16 g_whi[300000];
__device__ bf16 g_wlo[300000];

__device__ int   g_rowptrA[NNODES + 1];
__device__ int2  g_edgeA[NEDGES];   // (col, val-bits) interleaved
__device__ int   g_rowptrL[NNODES + 1];
__device__ int2  g_edgeL[NEDGES];
__device__ int   g_cntA[NNODES];    // doubles as scatter cursor (re-zeroed in scan_final)
__device__ int   g_cntL[NNODES];
__device__ int   g_part[2][128];
__device__ int   g_partex[2][128];

// weight packing offsets
#define OFF_GCN_W0 0
#define OFF_PAI1_0 65536
#define OFF_PAI2_0 131072
#define OFF_W1_W0  196608
#define OFF_W2_W0  212992
#define OFF_GCN_W1 229376
#define OFF_PAI1_1 245760
#define OFF_PAI2_1 249856
#define OFF_W1_W1  266240
#define OFF_W2_W1  270336

// ---------------- CSR build (A and L merged via blockIdx.y) ----------------
__global__ void k_zero2(int* a, int* b, int n) {
    int i = blockIdx.x * blockDim.x + threadIdx.x;
    if (i < n) { a[i] = 0; b[i] = 0; }
}

__global__ void k_count2(const int* __restrict__ rowsA, const int* __restrict__ rowsL,
                         int* __restrict__ cntA, int* __restrict__ cntL, int E) {
    int e = blockIdx.x * blockDim.x + threadIdx.x;
    if (e >= E) return;
    if (blockIdx.y == 0) atomicAdd(&cntA[rowsA[e]], 1);
    else                 atomicAdd(&cntL[rowsL[e]], 1);
}

__global__ void k_scan_reduce2(const int* __restrict__ cntA, const int* __restrict__ cntL,
                               int n) {
    const int* cnt = blockIdx.y == 0 ? cntA : cntL;
    int chunk = blockIdx.x;
    int tid = threadIdx.x;
    int base = chunk * 1024;
    int s = 0;
    for (int i = tid; i < 1024; i += 256) {
        int idx = base + i;
        if (idx < n) s += cnt[idx];
    }
#pragma unroll
    for (int off = 16; off > 0; off >>= 1) s += __shfl_down_sync(0xffffffffu, s, off);
    __shared__ int ws[8];
    if ((tid & 31) == 0) ws[tid >> 5] = s;
    __syncthreads();
    if (tid < 8) {
        int v = ws[tid];
#pragma unroll
        for (int off = 4; off > 0; off >>= 1) v += __shfl_down_sync(0xffu, v, off);
        if (tid == 0) g_part[blockIdx.y][chunk] = v;
    }
}

__global__ void k_scan_part2(int np) {
    __shared__ int sh[128];
    int g = blockIdx.y;
    int tid = threadIdx.x;
    int v = (tid < np) ? g_part[g][tid] : 0;
    sh[tid] = v;
    __syncthreads();
    for (int off = 1; off < 128; off <<= 1) {
        int t = (tid >= off) ? sh[tid - off] : 0;
        __syncthreads();
        sh[tid] += t;
        __syncthreads();
    }
    if (tid < np) g_partex[g][tid] = sh[tid] - v;
}

// reads cnt, writes rowptr, then RE-ZEROES cnt so scatter can use it as cursor
__global__ void k_scan_final2(int* __restrict__ cntA, int* __restrict__ cntL,
                              int* __restrict__ rowptrA, int* __restrict__ rowptrL, int n) {
    __shared__ int sh[256];
    int g = blockIdx.y;
    int* cnt = g == 0 ? cntA : cntL;
    int* rowptr = g == 0 ? rowptrA : rowptrL;
    int chunk = blockIdx.x;
    int tid = threadIdx.x;
    int base = chunk * 1024;
    int v[4];
    int s = 0;
#pragma unroll
    for (int i = 0; i < 4; i++) {
        int idx = base + tid * 4 + i;
        v[i] = (idx < n) ? cnt[idx] : 0;
        if (idx < n) cnt[idx] = 0;
        s += v[i];
    }
    sh[tid] = s;
    __syncthreads();
    for (int off = 1; off < 256; off <<= 1) {
        int t = (tid >= off) ? sh[tid - off] : 0;
        __syncthreads();
        sh[tid] += t;
        __syncthreads();
    }
    int run = (tid ? sh[tid - 1] : 0) + g_partex[g][chunk];
#pragma unroll
    for (int i = 0; i < 4; i++) {
        run += v[i];
        int idx = base + tid * 4 + i;
        if (idx < n) rowptr[idx + 1] = run;
    }
    if (chunk == 0 && tid == 0) rowptr[0] = 0;
}

__global__ void k_scatter2(const int* __restrict__ idxA, const float* __restrict__ valsA,
                           const int* __restrict__ idxL, const float* __restrict__ valsL,
                           const int* __restrict__ rowptrA, const int* __restrict__ rowptrL,
                           int* __restrict__ curA, int* __restrict__ curL,
                           int2* __restrict__ edgeA, int2* __restrict__ edgeL, int E) {
    int e = blockIdx.x * blockDim.x + threadIdx.x;
    if (e >= E) return;
    if (blockIdx.y == 0) {
        int r = idxA[e];
        int p = rowptrA[r] + atomicAdd(&curA[r], 1);
        edgeA[p] = make_int2(idxA[E + e], __float_as_int(valsA[e]));
    } else {
        int r = idxL[e];
        int p = rowptrL[r] + atomicAdd(&curL[r], 1);
        edgeL[p] = make_int2(idxL[E + e], __float_as_int(valsL[e]));
    }
}

// ---------------- fp32 -> bf16 hi/lo split (x + weights only) ----------------
__global__ void k_split(const float* __restrict__ src, bf16* __restrict__ hi,
                        bf16* __restrict__ lo, int n4) {
    int i = blockIdx.x * blockDim.x + threadIdx.x;
    if (i >= n4) return;
    float4 v = ((const float4*)src)[i];
    __nv_bfloat162 h01 = __floats2bfloat162_rn(v.x, v.y);
    __nv_bfloat162 h23 = __floats2bfloat162_rn(v.z, v.w);
    float lx = v.x - __bfloat162float(h01.x);
    float ly = v.y - __bfloat162float(h01.y);
    float lz = v.z - __bfloat162float(h23.x);
    float lw = v.w - __bfloat162float(h23.y);
    ((__nv_bfloat162*)hi)[i * 2] = h01;
    ((__nv_bfloat162*)hi)[i * 2 + 1] = h23;
    ((__nv_bfloat162*)lo)[i * 2] = __floats2bfloat162_rn(lx, ly);
    ((__nv_bfloat162*)lo)[i * 2 + 1] = __floats2bfloat162_rn(lz, lw);
}

struct WSplit {
    const float* src[10];
    int n4[10];
    int off[10];
};

__global__ void k_split_weights(WSplit ws, bf16* __restrict__ hi, bf16* __restrict__ lo) {
    int t = blockIdx.y;
    int i = blockIdx.x * blockDim.x + threadIdx.x;
    if (i >= ws.n4[t]) return;
    float4 v = ((const float4*)ws.src[t])[i];
    __nv_bfloat162 h01 = __floats2bfloat162_rn(v.x, v.y);
    __nv_bfloat162 h23 = __floats2bfloat162_rn(v.z, v.w);
    float lx = v.x - __bfloat162float(h01.x);
    float ly = v.y - __bfloat162float(h01.y);
    float lz = v.z - __bfloat162float(h23.x);
    float lw = v.w - __bfloat162float(h23.y);
    __nv_bfloat162* hp = (__nv_bfloat162*)(hi + ws.off[t]);
    __nv_bfloat162* lp = (__nv_bfloat162*)(lo + ws.off[t]);
    hp[i * 2] = h01;
    hp[i * 2 + 1] = h23;
    lp[i * 2] = __floats2bfloat162_rn(lx, ly);
    lp[i * 2 + 1] = __floats2bfloat162_rn(lz, lw);
}

// ---------------- activations ----------------
__device__ __forceinline__ float actf(float x) {
    float s1 = fmaxf(x - 0.1f, 0.f) - fmaxf(-x - 0.1f, 0.f);
    float s2 = fmaxf(x - 0.5f, 0.f) - fmaxf(-x - 0.5f, 0.f);
    return 1.8f * s1 - 0.8f * s2;
}

__device__ __forceinline__ void store_split4(bf16* __restrict__ hi, bf16* __restrict__ lo,
                                             size_t idx2, float a, float b, float c, float d) {
    __nv_bfloat162 h01 = __floats2bfloat162_rn(a, b);
    __nv_bfloat162 h23 = __floats2bfloat162_rn(c, d);
    float lx = a - __bfloat162float(h01.x);
    float ly = b - __bfloat162float(h01.y);
    float lz = c - __bfloat162float(h23.x);
    float lw = d - __bfloat162float(h23.y);
    ((__nv_bfloat162*)hi)[idx2] = h01;
    ((__nv_bfloat162*)hi)[idx2 + 1] = h23;
    ((__nv_bfloat162*)lo)[idx2] = __floats2bfloat162_rn(lx, ly);
    ((__nv_bfloat162*)lo)[idx2 + 1] = __floats2bfloat162_rn(lz, lw);
}

// ---------------- CSR SpMM: F4 variant (64-wide layers), edge prefetch ----------------
template <int F4>
__global__ __launch_bounds__(256, 8) void k_spmm_relu4(
        const int* __restrict__ rowptr, const int2* __restrict__ edge,
        const float* __restrict__ X,
        const float* __restrict__ bias, float* __restrict__ outF,
        bf16* __restrict__ outHi, bf16* __restrict__ outLo) {
    int t = blockIdx.x * blockDim.x + threadIdx.x;
    int row = t / F4;
    int f = t % F4;
    if (row >= NNODES) return;
    int s = rowptr[row], e = rowptr[row + 1];
    const float4* X4 = (const float4*)X;
    float4 acc = make_float4(0.f, 0.f, 0.f, 0.f);
    if (s < e) {
        int2 ev = __ldg(&edge[s]);
        for (int p = s; p < e; p++) {
            int2 evn = (p + 1 < e) ? __ldg(&edge[p + 1]) : ev;
            float v = __int_as_float(ev.y);
            float4 xv = X4[(size_t)ev.x * F4 + f];
            acc.x = fmaf(v, xv.x, acc.x);
            acc.y = fmaf(v, xv.y, acc.y);
            acc.z = fmaf(v, xv.z, acc.z);
            acc.w = fmaf(v, xv.w, acc.w);
            ev = evn;
        }
    }
    float4 b = ((const float4*)bias)[f];
    float ox = fmaxf(acc.x + b.x, 0.f);
    float oy = fmaxf(acc.y + b.y, 0.f);
    float oz = fmaxf(acc.z + b.z, 0.f);
    float ow = fmaxf(acc.w + b.w, 0.f);
    ((float4*)outF)[(size_t)row * F4 + f] = make_float4(ox, oy, oz, ow);
    store_split4(outHi, outLo, ((size_t)row * F4 + f) * 2, ox, oy, oz, ow);
}

template <int F4>
__global__ __launch_bounds__(256, 8) void k_spmm_embed4(
        const int* __restrict__ rowptr, const int2* __restrict__ edge,
        const float* __restrict__ X,
        const float* __restrict__ T,
        bf16* __restrict__ outHi, bf16* __restrict__ outLo) {
    int t = blockIdx.x * blockDim.x + threadIdx.x;
    int row = t / F4;
    int f = t % F4;
    if (row >= NNODES) return;
    int s = rowptr[row], e = rowptr[row + 1];
    const float4* X4 = (const float4*)X;
    float4 acc = make_float4(0.f, 0.f, 0.f, 0.f);
    if (s < e) {
        int2 ev = __ldg(&edge[s]);
        for (int p = s; p < e; p++) {
            int2 evn = (p + 1 < e) ? __ldg(&edge[p + 1]) : ev;
            float v = __int_as_float(ev.y);
            float4 xv = X4[(size_t)ev.x * F4 + f];
            acc.x = fmaf(v, xv.x, acc.x);
            acc.y = fmaf(v, xv.y, acc.y);
            acc.z = fmaf(v, xv.z, acc.z);
            acc.w = fmaf(v, xv.w, acc.w);
            ev = evn;
        }
    }
    float4 tv = ((const float4*)T)[(size_t)row * F4 + f];
    float ox = actf(tv.x - acc.x);
    float oy = actf(tv.y - acc.y);
    float oz = actf(tv.z - acc.z);
    float ow = actf(tv.w - acc.w);
    store_split4(outHi, outLo, ((size_t)row * F4 + f) * 2, ox, oy, oz, ow);
}

// ---------------- CSR SpMM: F8 variant (256-wide layers; one warp per row), edge prefetch ----
template <int F8>
__global__ __launch_bounds__(256, 6) void k_spmm_relu8(
        const int* __restrict__ rowptr, const int2* __restrict__ edge,
        const float* __restrict__ X,
        const float* __restrict__ bias, float* __restrict__ outF,
        bf16* __restrict__ outHi, bf16* __restrict__ outLo) {
    int t = blockIdx.x * blockDim.x + threadIdx.x;
    int row = t / F8;
    int f = t % F8;             // unit of 8 floats = 2 float4
    if (row >= NNODES) return;
    int s = rowptr[row], e = rowptr[row + 1];
    const float4* X4 = (const float4*)X;
    float4 acc0 = make_float4(0.f, 0.f, 0.f, 0.f);
    float4 acc1 = make_float4(0.f, 0.f, 0.f, 0.f);
    if (s < e) {
        int2 ev = __ldg(&edge[s]);
        for (int p = s; p < e; p++) {
            int2 evn = (p + 1 < e) ? __ldg(&edge[p + 1]) : ev;
            float v = __int_as_float(ev.y);
            size_t base = (size_t)ev.x * (F8 * 2) + f * 2;
            float4 x0 = X4[base];
            float4 x1 = X4[base + 1];
            acc0.x = fmaf(v, x0.x, acc0.x); acc0.y = fmaf(v, x0.y, acc0.y);
            acc0.z = fmaf(v, x0.z, acc0.z); acc0.w = fmaf(v, x0.w, acc0.w);
            acc1.x = fmaf(v, x1.x, acc1.x); acc1.y = fmaf(v, x1.y, acc1.y);
            acc1.z = fmaf(v, x1.z, acc1.z); acc1.w = fmaf(v, x1.w, acc1.w);
            ev = evn;
        }
    }
    float4 b0 = ((const float4*)bias)[f * 2];
    float4 b1 = ((const float4*)bias)[f * 2 + 1];
    float o0x = fmaxf(acc0.x + b0.x, 0.f), o0y = fmaxf(acc0.y + b0.y, 0.f);
    float o0z = fmaxf(acc0.z + b0.z, 0.f), o0w = fmaxf(acc0.w + b0.w, 0.f);
    float o1x = fmaxf(acc1.x + b1.x, 0.f), o1y = fmaxf(acc1.y + b1.y, 0.f);
    float o1z = fmaxf(acc1.z + b1.z, 0.f), o1w = fmaxf(acc1.w + b1.w, 0.f);
    size_t o4 = (size_t)row * (F8 * 2) + f * 2;
    ((float4*)outF)[o4] = make_float4(o0x, o0y, o0z, o0w);
    ((float4*)outF)[o4 + 1] = make_float4(o1x, o1y, o1z, o1w);
    store_split4(outHi, outLo, o4 * 2, o0x, o0y, o0z, o0w);
    store_split4(outHi, outLo, o4 * 2 + 2, o1x, o1y, o1z, o1w);
}

template <int F8>
__global__ __launch_bounds__(256, 6) void k_spmm_embed8(
        const int* __restrict__ rowptr, const int2* __restrict__ edge,
        const float* __restrict__ X,
        const float* __restrict__ T,
        bf16* __restrict__ outHi, bf16* __restrict__ outLo) {
    int t = blockIdx.x * blockDim.x + threadIdx.x;
    int row = t / F8;
    int f = t % F8;
    if (row >= NNODES) return;
    int s = rowptr[row], e = rowptr[row + 1];
    const float4* X4 = (const float4*)X;
    float4 acc0 = make_float4(0.f, 0.f, 0.f, 0.f);
    float4 acc1 = make_float4(0.f, 0.f, 0.f, 0.f);
    if (s < e) {
        int2 ev = __ldg(&edge[s]);
        for (int p = s; p < e; p++) {
            int2 evn = (p + 1 < e) ? __ldg(&edge[p + 1]) : ev;
            float v = __int_as_float(ev.y);
            size_t base = (size_t)ev.x * (F8 * 2) + f * 2;
            float4 x0 = X4[base];
            float4 x1 = X4[base + 1];
            acc0.x = fmaf(v, x0.x, acc0.x); acc0.y = fmaf(v, x0.y, acc0.y);
            acc0.z = fmaf(v, x0.z, acc0.z); acc0.w = fmaf(v, x0.w, acc0.w);
            acc1.x = fmaf(v, x1.x, acc1.x); acc1.y = fmaf(v, x1.y, acc1.y);
            acc1.z = fmaf(v, x1.z, acc1.z); acc1.w = fmaf(v, x1.w, acc1.w);
            ev = evn;
        }
    }
    size_t o4 = (size_t)row * (F8 * 2) + f * 2;
    float4 t0 = ((const float4*)T)[o4];
    float4 t1 = ((const float4*)T)[o4 + 1];
    float o0x = actf(t0.x - acc0.x), o0y = actf(t0.y - acc0.y);
    float o0z = actf(t0.z - acc0.z), o0w = actf(t0.w - acc0.w);
    float o1x = actf(t1.x - acc1.x), o1y = actf(t1.y - acc1.y);
    float o1z = actf(t1.z - acc1.z), o1w = actf(t1.w - acc1.w);
    store_split4(outHi, outLo, o4 * 2, o0x, o0y, o0z, o0w);
    store_split4(outHi, outLo, o4 * 2 + 2, o1x, o1y, o1z, o1w);
}

// ---------------- tensor-core GEMM (pre-split bf16x3, cp.async + ldmatrix) ----------------
__device__ __forceinline__ uint32_t s2u(const void* p) {
    return (uint32_t)__cvta_generic_to_shared(p);
}
__device__ __forceinline__ int aoff(int row, int k) {
    return row * 64 + (((k >> 3) ^ ((row >> 1) & 3)) << 4) + ((k & 7) << 1);
}
__device__ __forceinline__ int boff(int kr, int n) {
    return kr * 128 + (((n >> 3) ^ (kr & 7)) << 4) + ((n & 7) << 1);
}
__device__ __forceinline__ void cp16(uint32_t dst, const void* src) {
    asm volatile("cp.async.cg.shared.global [%0], [%1], 16;\n" ::"r"(dst), "l"(src));
}
__device__ __forceinline__ void ldm_x4(uint32_t addr, uint32_t& r0, uint32_t& r1,
                                       uint32_t& r2, uint32_t& r3) {
    asm volatile("ldmatrix.sync.aligned.m8n8.x4.shared.b16 {%0,%1,%2,%3}, [%4];\n"
                 : "=r"(r0), "=r"(r1), "=r"(r2), "=r"(r3) : "r"(addr));
}
__device__ __forceinline__ void ldm_x4t(uint32_t addr, uint32_t& r0, uint32_t& r1,
                                        uint32_t& r2, uint32_t& r3) {
    asm volatile("ldmatrix.sync.aligned.m8n8.x4.trans.shared.b16 {%0,%1,%2,%3}, [%4];\n"
                 : "=r"(r0), "=r"(r1), "=r"(r2), "=r"(r3) : "r"(addr));
}
__device__ __forceinline__ void mma_bf16(float& d0, float& d1, float& d2, float& d3,
                                         uint32_t a0, uint32_t a1, uint32_t a2, uint32_t a3,
                                         uint32_t b0, uint32_t b1) {
    asm volatile(
        "mma.sync.aligned.m16n8k16.row.col.f32.bf16.bf16.f32 "
        "{%0,%1,%2,%3}, {%4,%5,%6,%7}, {%8,%9}, {%0,%1,%2,%3};"
        : "+f"(d0), "+f"(d1), "+f"(d2), "+f"(d3)
        : "r"(a0), "r"(a1), "r"(a2), "r"(a3), "r"(b0), "r"(b1));
}

__global__ __launch_bounds__(256) void k_gemm_tc(
    const bf16* __restrict__ A1hi, const bf16* __restrict__ A1lo, int K1,
    const bf16* __restrict__ B1hi, const bf16* __restrict__ B1lo,
    const bf16* __restrict__ A2hi, const bf16* __restrict__ A2lo, int K2,
    const bf16* __restrict__ B2hi, const bf16* __restrict__ B2lo,
    float* __restrict__ C, int M, int Nc,
    const float* __restrict__ bias, int actFlag)
{
    __shared__ __align__(16) bf16 sA[2][2][128 * 32];
    __shared__ __align__(16) bf16 sB[2][2][32 * 64];

    int tid = threadIdx.x;
    int warp = tid >> 5, lane = tid & 31;
    int wm = warp & 3;
    int wn = warp >> 2;
    int bn = blockIdx.x * 64;
    int bm = blockIdx.y * 128;

    float acc[2][4][4];
#pragma unroll
    for (int i = 0; i < 2; i++)
#pragma unroll
        for (int j = 0; j < 4; j++)
#pragma unroll
            for (int c = 0; c < 4; c++) acc[i][j][c] = 0.f;

    const int T = (K1 + K2) / 32;

    int arow0 = tid >> 2, ac0 = tid & 3;
    int arow1 = (tid + 256) >> 2, ac1 = tid & 3;
    int garow0 = bm + arow0; if (garow0 >= M) garow0 = M - 1;
    int garow1 = bm + arow1; if (garow1 >= M) garow1 = M - 1;
    int bkr = tid >> 3, bc = tid & 7;

    auto loadTile = [&](int t, int stage) {
        int k0 = t * 32;
        const bf16 *Ahi, *Alo, *Bhi, *Blo;
        int kloc, K;
        if (k0 < K1) { Ahi = A1hi; Alo = A1lo; Bhi = B1hi; Blo = B1lo; kloc = k0; K = K1; }
        else         { Ahi = A2hi; Alo = A2lo; Bhi = B2hi; Blo = B2lo; kloc = k0 - K1; K = K2; }
        uint32_t sa_hi = s2u(&sA[stage][0][0]);
        uint32_t sa_lo = s2u(&sA[stage][1][0]);
        uint32_t sb_hi = s2u(&sB[stage][0][0]);
        uint32_t sb_lo = s2u(&sB[stage][1][0]);
        int so0 = aoff(arow0, ac0 * 8);
        int so1 = aoff(arow1, ac1 * 8);
        size_t g0 = (size_t)garow0 * K + kloc + ac0 * 8;
        size_t g1 = (size_t)garow1 * K + kloc + ac1 * 8;
        cp16(sa_hi + so0, Ahi + g0);
        cp16(sa_hi + so1, Ahi + g1);
        cp16(sa_lo + so0, Alo + g0);
        cp16(sa_lo + so1, Alo + g1);
        int sob = boff(bkr, bc * 8);
        size_t gb = (size_t)(kloc + bkr) * Nc + bn + bc * 8;
        cp16(sb_hi + sob, Bhi + gb);
        cp16(sb_lo + sob, Blo + gb);
        asm volatile("cp.async.commit_group;\n");
    };

    loadTile(0, 0);

    int a_r = (lane & 7) + ((lane & 8) ? 8 : 0);
    int a_k = (lane & 16) ? 8 : 0;
    int b_k = (lane & 7) + ((lane & 8) ? 8 : 0);
    int b_n = (lane & 16) ? 8 : 0;

    for (int t = 0; t < T; t++) {
        int s = t & 1;
        if (t + 1 < T) {
            loadTile(t + 1, (t + 1) & 1);
            asm volatile("cp.async.wait_group 1;\n");
        } else {
            asm volatile("cp.async.wait_group 0;\n");
        }
        __syncthreads();

        uint32_t sa_hi = s2u(&sA[s][0][0]);
        uint32_t sa_lo = s2u(&sA[s][1][0]);
        uint32_t sb_hi = s2u(&sB[s][0][0]);
        uint32_t sb_lo = s2u(&sB[s][1][0]);

#pragma unroll
        for (int ks = 0; ks < 32; ks += 16) {
            uint32_t ahi[2][4], alo[2][4], bhi[4][2], blo[4][2];
#pragma unroll
            for (int mf = 0; mf < 2; mf++) {
                int row = wm * 32 + mf * 16 + a_r;
                int off = aoff(row, ks + a_k);
                ldm_x4(sa_hi + off, ahi[mf][0], ahi[mf][1], ahi[mf][2], ahi[mf][3]);
                ldm_x4(sa_lo + off, alo[mf][0], alo[mf][1], alo[mf][2], alo[mf][3]);
            }
#pragma unroll
            for (int p = 0; p < 2; p++) {
                int kr = ks + b_k;
                int n = wn * 32 + p * 16 + b_n;
                int off = boff(kr, n);
                ldm_x4t(sb_hi + off, bhi[2 * p][0], bhi[2 * p][1], bhi[2 * p + 1][0], bhi[2 * p + 1][1]);
                ldm_x4t(sb_lo + off, blo[2 * p][0], blo[2 * p][1], blo[2 * p + 1][0], blo[2 * p + 1][1]);
            }
#pragma unroll
            for (int mf = 0; mf < 2; mf++)
#pragma unroll
                for (int nf = 0; nf < 4; nf++) {
                    float* d = acc[mf][nf];
                    mma_bf16(d[0], d[1], d[2], d[3],
                             ahi[mf][0], ahi[mf][1], ahi[mf][2], ahi[mf][3],
                             bhi[nf][0], bhi[nf][1]);
                    mma_bf16(d[0], d[1], d[2], d[3],
                             ahi[mf][0], ahi[mf][1], ahi[mf][2], ahi[mf][3],
                             blo[nf][0], blo[nf][1]);
                    mma_bf16(d[0], d[1], d[2], d[3],
                             alo[mf][0], alo[mf][1], alo[mf][2], alo[mf][3],
                             bhi[nf][0], bhi[nf][1]);
                }
        }
        __syncthreads();
    }

#pragma unroll
    for (int mf = 0; mf < 2; mf++) {
        int row0 = bm + wm * 32 + mf * 16 + (lane >> 2);
#pragma unroll
        for (int nf = 0; nf < 4; nf++) {
            int col = bn + wn * 32 + nf * 8 + (lane & 3) * 2;
            float b0 = bias ? bias[col] : 0.f;
            float b1 = bias ? bias[col + 1] : 0.f;
            float* d = acc[mf][nf];
            float c0 = d[0] + b0, c1 = d[1] + b1, c2 = d[2] + b0, c3 = d[3] + b1;
            if (actFlag) { c0 = tanhf(c0); c1 = tanhf(c1); c2 = tanhf(c2); c3 = tanhf(c3); }
            if (row0 < M) *(float2*)(C + (size_t)row0 * Nc + col) = make_float2(c0, c1);
            if (row0 + 8 < M) *(float2*)(C + (size_t)(row0 + 8) * Nc + col) = make_float2(c2, c3);
        }
    }
}

// ---------------- host orchestration ----------------
static inline void gemm2(const bf16* A1h, const bf16* A1l, int K1, const bf16* B1h, const bf16* B1l,
                         const bf16* A2h, const bf16* A2l, int K2, const bf16* B2h, const bf16* B2l,
                         float* C, int M, int Nc, const float* bias, int actFlag) {
    dim3 grid(Nc / 64, (M + 127) / 128);
    k_gemm_tc<<<grid, 256>>>(A1h, A1l, K1, B1h, B1l, A2h, A2l, K2, B2h, B2l,
                             C, M, Nc, bias, actFlag);
}
static inline void gemm1(const bf16* Ah, const bf16* Al, int K, const bf16* Bh, const bf16* Bl,
                         float* C, int M, int Nc, const float* bias, int actFlag) {
    gemm2(Ah, Al, K, Bh, Bl, nullptr, nullptr, 0, nullptr, nullptr, C, M, Nc, bias, actFlag);
}

extern "C" void kernel_launch(void* const* d_in, const int* in_sizes, int n_in,
                              void* d_out, int out_size) {
    (void)in_sizes; (void)n_in; (void)out_size;
    const float* x      = (const float*)d_in[0];
    const int*   A_idx  = (const int*)d_in[1];
    const float* A_val  = (const float*)d_in[2];
    const int*   L_idx  = (const int*)d_in[3];
    const float* L_val  = (const float*)d_in[4];
    const float* gcn_w0 = (const float*)d_in[5];
    const float* gcn_b0 = (const float*)d_in[6];
    const float* pai1_0 = (const float*)d_in[7];
    const float* pai2_0 = (const float*)d_in[8];
    const float* w1_w0  = (const float*)d_in[9];
    const float* w1_b0  = (const float*)d_in[10];
    const float* w2_w0  = (const float*)d_in[11];
    const float* w2_b0  = (const float*)d_in[12];
    const float* gcn_w1 = (const float*)d_in[13];
    const float* gcn_b1 = (const float*)d_in[14];
    const float* pai1_1 = (const float*)d_in[15];
    const float* pai2_1 = (const float*)d_in[16];
    const float* w1_w1  = (const float*)d_in[17];
    const float* w1_b1  = (const float*)d_in[18];
    const float* w2_w1  = (const float*)d_in[19];
    const float* w2_b1  = (const float*)d_in[20];

    float* out = (float*)d_out;
    float* out_ztp0 = out;
    float* out_ztp1 = out + (size_t)NNODES * FOUT;
    float* out_zem0 = out + (size_t)2 * NNODES * FOUT;
    float* out_zem1 = out + (size_t)3 * NNODES * FOUT;

    float *buf0, *buf1, *buf2;
    bf16 *xhi, *xlo, *zhi, *zlo, *whi, *wlo;
    int *rowptrA, *rowptrL, *cntA, *cntL;
    int2 *edgeA, *edgeL;
    cudaGetSymbolAddress((void**)&buf0, g_buf0);
    cudaGetSymbolAddress((void**)&buf1, g_buf1);
    cudaGetSymbolAddress((void**)&buf2, g_buf2);
    cudaGetSymbolAddress((void**)&xhi, g_xhi);
    cudaGetSymbolAddress((void**)&xlo, g_xlo);
    cudaGetSymbolAddress((void**)&zhi, g_zhi);
    cudaGetSymbolAddress((void**)&zlo, g_zlo);
    cudaGetSymbolAddress((void**)&whi, g_whi);
    cudaGetSymbolAddress((void**)&wlo, g_wlo);
    cudaGetSymbolAddress((void**)&rowptrA, g_rowptrA);
    cudaGetSymbolAddress((void**)&edgeA, g_edgeA);
    cudaGetSymbolAddress((void**)&rowptrL, g_rowptrL);
    cudaGetSymbolAddress((void**)&edgeL, g_edgeL);
    cudaGetSymbolAddress((void**)&cntA, g_cntA);
    cudaGetSymbolAddress((void**)&cntL, g_cntL);

    const int TB = 256;
    int gbN = (NNODES + TB - 1) / TB;
    int gbE = (NEDGES + TB - 1) / TB;
    int nChunks = (NNODES + 1023) / 1024;

    // ---- splits first, then CSR count/scan, GEMM0 at slot 6 ----
    {
        int n4 = NNODES * FDIN / 4;
        k_split<<<(n4 + TB - 1) / TB, TB>>>(x, xhi, xlo, n4);                 // 1
        WSplit ws;
        ws.src[0] = gcn_w0; ws.n4[0] = 65536 / 4; ws.off[0] = OFF_GCN_W0;
        ws.src[1] = pai1_0; ws.n4[1] = 65536 / 4; ws.off[1] = OFF_PAI1_0;
        ws.src[2] = pai2_0; ws.n4[2] = 65536 / 4; ws.off[2] = OFF_PAI2_0;
        ws.src[3] = w1_w0;  ws.n4[3] = 16384 / 4; ws.off[3] = OFF_W1_W0;
        ws.src[4] = w2_w0;  ws.n4[4] = 16384 / 4; ws.off[4] = OFF_W2_W0;
        ws.src[5] = gcn_w1; ws.n4[5] = 16384 / 4; ws.off[5] = OFF_GCN_W1;
        ws.src[6] = pai1_1; ws.n4[6] = 4096 / 4;  ws.off[6] = OFF_PAI1_1;
        ws.src[7] = pai2_1; ws.n4[7] = 16384 / 4; ws.off[7] = OFF_PAI2_1;
        ws.src[8] = w1_w1;  ws.n4[8] = 4096 / 4;  ws.off[8] = OFF_W1_W1;
        ws.src[9] = w2_w1;  ws.n4[9] = 4096 / 4;  ws.off[9] = OFF_W2_W1;
        dim3 grid(64, 10);
        k_split_weights<<<grid, TB>>>(ws, whi, wlo);                          // 2
    }
    k_zero2<<<gbN, TB>>>(cntA, cntL, NNODES);                                 // 3
    {
        dim3 g(gbE, 2);
        k_count2<<<g, TB>>>(A_idx, L_idx, cntA, cntL, NEDGES);                // 4
    }
    {
        dim3 g(nChunks, 2);
        k_scan_reduce2<<<g, 256>>>(cntA, cntL, NNODES);                       // 5
    }
    // layer-0 GCN GEMM — slot 6 (ncu -s 5 profiles this)
    gemm1(xhi, xlo, FDIN, whi + OFF_GCN_W0, wlo + OFF_GCN_W0, buf0, NNODES, FH, nullptr, 0);
    {
        dim3 g1(1, 2);
        k_scan_part2<<<g1, 128>>>(nChunks);
        dim3 g(nChunks, 2);
        k_scan_final2<<<g, 256>>>(cntA, cntL, rowptrA, rowptrL, NNODES);
        dim3 ge(gbE, 2);
        // cnt arrays re-zeroed by scan_final -> reused as scatter cursors
        k_scatter2<<<ge, TB>>>(A_idx, A_val, L_idx, L_val, rowptrA, rowptrL,
                               cntA, cntL, edgeA, edgeL, NEDGES);
    }

    // ================= layer 0 (din=256 -> h=256) =================
    {
        int threads = NNODES * (FH / 8);
        k_spmm_relu8<FH / 8><<<(threads + TB - 1) / TB, TB>>>(rowptrA, edgeA, buf0,
                                                              gcn_b0, buf1, zhi, zlo);
    }
    gemm1(zhi, zlo, FH, whi + OFF_W1_W0, wlo + OFF_W1_W0, out_ztp0, NNODES, FOUT, w1_b0, 1);
    gemm2(zhi, zlo, FH, whi + OFF_PAI1_0, wlo + OFF_PAI1_0,
          xhi, xlo, FDIN, whi + OFF_PAI2_0, wlo + OFF_PAI2_0,
          buf2, NNODES, FH, nullptr, 0);
    {
        int threads = NNODES * (FH / 8);
        k_spmm_embed8<FH / 8><<<(threads + TB - 1) / TB, TB>>>(rowptrL, edgeL, buf1,
                                                               buf2, zhi, zlo);
    }
    gemm1(zhi, zlo, FH, whi + OFF_W2_W0, wlo + OFF_W2_W0, out_zem0, NNODES, FOUT, w2_b0, 1);

    // ================= layer 1 (h=256 -> dout=64) =================
    gemm1(zhi, zlo, FH, whi + OFF_GCN_W1, wlo + OFF_GCN_W1, buf0, NNODES, FOUT, nullptr, 0);
    {
        int threads = NNODES * (FOUT / 4);
        k_spmm_relu4<FOUT / 4><<<(threads + TB - 1) / TB, TB>>>(rowptrA, edgeA, buf0,
                                                                gcn_b1, buf1, zhi, zlo);
    }
    gemm1(zhi, zlo, FOUT, whi + OFF_W1_W1, wlo + OFF_W1_W1, out_ztp1, NNODES, FOUT, w1_b1, 1);
    gemm2(zhi, zlo, FOUT, whi + OFF_PAI1_1, wlo + OFF_PAI1_1,
          xhi, xlo, FDIN, whi + OFF_PAI2_1, wlo + OFF_PAI2_1,
          buf2, NNODES, FOUT, nullptr, 0);
    {
        int threads = NNODES * (FOUT / 4);
        k_spmm_embed4<FOUT / 4><<<(threads + TB - 1) / TB, TB>>>(rowptrL, edgeL, buf1,
                                                                 buf2, zhi, zlo);
    }
    gemm1(zhi, zlo, FOUT, whi + OFF_W2_W1, wlo + OFF_W2_W1, out_zem1, NNODES, FOUT, w2_b1, 1);
}

// round 17
// speedup vs baseline: 1.0199x; 1.0199x over previous
#include <cuda_runtime.h>
#include <cuda_bf16.h>
#include <math.h>
#include <stdint.h>

#define NNODES 100000
#define NEDGES 1600000
#define FDIN   256
#define FH     256
#define FOUT   64

typedef __nv_bfloat16 bf16;

// ---------------- scratch (device globals; no runtime allocation) ----------------
__device__ float g_buf0[(size_t)NNODES * 256];
__device__ float g_buf1[(size_t)NNODES * 256];
__device__ float g_buf2[(size_t)NNODES * 256];

__device__ bf16 g_xhi[(size_t)NNODES * 256];
__device__ bf16 g_xlo[(size_t)NNODES * 256];
__device__ bf16 g_zhi[(size_t)NNODES * 256];
__device__ bf16 g_zlo[(size_t)NNODES * 256];
__device__ bf16 g_whi[300000];
__device__ bf16 g_wlo[300000];
__device__ bf16 g_wb1hi[32768];   // [256][128] = [w2_w0 | gcn_w1]
__device__ bf16 g_wb1lo[32768];

__device__ int   g_rowptrA[NNODES + 1];
__device__ int2  g_edgeA[NEDGES];   // (col, val-bits) interleaved
__device__ int   g_rowptrL[NNODES + 1];
__device__ int2  g_edgeL[NEDGES];
__device__ int   g_cntA[NNODES];    // doubles as scatter cursor (re-zeroed in scan_final)
__device__ int   g_cntL[NNODES];
__device__ int   g_part[2][128];
__device__ int   g_partex[2][128];

// weight packing offsets
#define OFF_GCN_W0 0
#define OFF_PAI1_0 65536
#define OFF_PAI2_0 131072
#define OFF_W1_W0  196608
#define OFF_W2_W0  212992
#define OFF_GCN_W1 229376
#define OFF_PAI1_1 245760
#define OFF_PAI2_1 249856
#define OFF_W1_W1  266240
#define OFF_W2_W1  270336

// ---------------- CSR build (A and L merged via blockIdx.y) ----------------
__global__ void k_zero2(int* a, int* b, int n) {
    int i = blockIdx.x * blockDim.x + threadIdx.x;
    if (i < n) { a[i] = 0; b[i] = 0; }
}

__global__ void k_count2(const int* __restrict__ rowsA, const int* __restrict__ rowsL,
                         int* __restrict__ cntA, int* __restrict__ cntL, int E) {
    int e = blockIdx.x * blockDim.x + threadIdx.x;
    if (e >= E) return;
    if (blockIdx.y == 0) atomicAdd(&cntA[rowsA[e]], 1);
    else                 atomicAdd(&cntL[rowsL[e]], 1);
}

__global__ void k_scan_reduce2(const int* __restrict__ cntA, const int* __restrict__ cntL,
                               int n) {
    const int* cnt = blockIdx.y == 0 ? cntA : cntL;
    int chunk = blockIdx.x;
    int tid = threadIdx.x;
    int base = chunk * 1024;
    int s = 0;
    for (int i = tid; i < 1024; i += 256) {
        int idx = base + i;
        if (idx < n) s += cnt[idx];
    }
#pragma unroll
    for (int off = 16; off > 0; off >>= 1) s += __shfl_down_sync(0xffffffffu, s, off);
    __shared__ int ws[8];
    if ((tid & 31) == 0) ws[tid >> 5] = s;
    __syncthreads();
    if (tid < 8) {
        int v = ws[tid];
#pragma unroll
        for (int off = 4; off > 0; off >>= 1) v += __shfl_down_sync(0xffu, v, off);
        if (tid == 0) g_part[blockIdx.y][chunk] = v;
    }
}

__global__ void k_scan_part2(int np) {
    __shared__ int sh[128];
    int g = blockIdx.y;
    int tid = threadIdx.x;
    int v = (tid < np) ? g_part[g][tid] : 0;
    sh[tid] = v;
    __syncthreads();
    for (int off = 1; off < 128; off <<= 1) {
        int t = (tid >= off) ? sh[tid - off] : 0;
        __syncthreads();
        sh[tid] += t;
        __syncthreads();
    }
    if (tid < np) g_partex[g][tid] = sh[tid] - v;
}

// reads cnt, writes rowptr, then RE-ZEROES cnt so scatter can use it as cursor
__global__ void k_scan_final2(int* __restrict__ cntA, int* __restrict__ cntL,
                              int* __restrict__ rowptrA, int* __restrict__ rowptrL, int n) {
    __shared__ int sh[256];
    int g = blockIdx.y;
    int* cnt = g == 0 ? cntA : cntL;
    int* rowptr = g == 0 ? rowptrA : rowptrL;
    int chunk = blockIdx.x;
    int tid = threadIdx.x;
    int base = chunk * 1024;
    int v[4];
    int s = 0;
#pragma unroll
    for (int i = 0; i < 4; i++) {
        int idx = base + tid * 4 + i;
        v[i] = (idx < n) ? cnt[idx] : 0;
        if (idx < n) cnt[idx] = 0;
        s += v[i];
    }
    sh[tid] = s;
    __syncthreads();
    for (int off = 1; off < 256; off <<= 1) {
        int t = (tid >= off) ? sh[tid - off] : 0;
        __syncthreads();
        sh[tid] += t;
        __syncthreads();
    }
    int run = (tid ? sh[tid - 1] : 0) + g_partex[g][chunk];
#pragma unroll
    for (int i = 0; i < 4; i++) {
        run += v[i];
        int idx = base + tid * 4 + i;
        if (idx < n) rowptr[idx + 1] = run;
    }
    if (chunk == 0 && tid == 0) rowptr[0] = 0;
}

__global__ void k_scatter2(const int* __restrict__ idxA, const float* __restrict__ valsA,
                           const int* __restrict__ idxL, const float* __restrict__ valsL,
                           const int* __restrict__ rowptrA, const int* __restrict__ rowptrL,
                           int* __restrict__ curA, int* __restrict__ curL,
                           int2* __restrict__ edgeA, int2* __restrict__ edgeL, int E) {
    int e = blockIdx.x * blockDim.x + threadIdx.x;
    if (e >= E) return;
    if (blockIdx.y == 0) {
        int r = idxA[e];
        int p = rowptrA[r] + atomicAdd(&curA[r], 1);
        edgeA[p] = make_int2(idxA[E + e], __float_as_int(valsA[e]));
    } else {
        int r = idxL[e];
        int p = rowptrL[r] + atomicAdd(&curL[r], 1);
        edgeL[p] = make_int2(idxL[E + e], __float_as_int(valsL[e]));
    }
}

// ---------------- fp32 -> bf16 hi/lo split ----------------
__device__ __forceinline__ void split1(float v, bf16& h, bf16& l) {
    h = __float2bfloat16(v);
    l = __float2bfloat16(v - __bfloat162float(h));
}

__global__ void k_split(const float* __restrict__ src, bf16* __restrict__ hi,
                        bf16* __restrict__ lo, int n4) {
    int i = blockIdx.x * blockDim.x + threadIdx.x;
    if (i >= n4) return;
    float4 v = ((const float4*)src)[i];
    __nv_bfloat162 h01 = __floats2bfloat162_rn(v.x, v.y);
    __nv_bfloat162 h23 = __floats2bfloat162_rn(v.z, v.w);
    float lx = v.x - __bfloat162float(h01.x);
    float ly = v.y - __bfloat162float(h01.y);
    float lz = v.z - __bfloat162float(h23.x);
    float lw = v.w - __bfloat162float(h23.y);
    ((__nv_bfloat162*)hi)[i * 2] = h01;
    ((__nv_bfloat162*)hi)[i * 2 + 1] = h23;
    ((__nv_bfloat162*)lo)[i * 2] = __floats2bfloat162_rn(lx, ly);
    ((__nv_bfloat162*)lo)[i * 2 + 1] = __floats2bfloat162_rn(lz, lw);
}

struct WSplit {
    const float* src[10];
    int n4[10];
    int off[10];
};

__global__ void k_split_weights(WSplit ws, bf16* __restrict__ hi, bf16* __restrict__ lo) {
    int t = blockIdx.y;
    int i = blockIdx.x * blockDim.x + threadIdx.x;
    if (i >= ws.n4[t]) return;
    float4 v = ((const float4*)ws.src[t])[i];
    __nv_bfloat162 h01 = __floats2bfloat162_rn(v.x, v.y);
    __nv_bfloat162 h23 = __floats2bfloat162_rn(v.z, v.w);
    float lx = v.x - __bfloat162float(h01.x);
    float ly = v.y - __bfloat162float(h01.y);
    float lz = v.z - __bfloat162float(h23.x);
    float lw = v.w - __bfloat162float(h23.y);
    __nv_bfloat162* hp = (__nv_bfloat162*)(hi + ws.off[t]);
    __nv_bfloat162* lp = (__nv_bfloat162*)(lo + ws.off[t]);
    hp[i * 2] = h01;
    hp[i * 2 + 1] = h23;
    lp[i * 2] = __floats2bfloat162_rn(lx, ly);
    lp[i * 2 + 1] = __floats2bfloat162_rn(lz, lw);
}

// build WB1 = [256][128] : [w2_w0 | gcn_w1], split to hi/lo
__global__ void k_build_wb1(const float* __restrict__ w2_w0, const float* __restrict__ gcn_w1,
                            bf16* __restrict__ hi, bf16* __restrict__ lo) {
    int i = blockIdx.x * blockDim.x + threadIdx.x;
    if (i >= 256 * 128) return;
    int r = i >> 7, c = i & 127;
    float v = (c < 64) ? w2_w0[r * 64 + c] : gcn_w1[r * 64 + (c - 64)];
    bf16 h, l;
    split1(v, h, l);
    hi[i] = h; lo[i] = l;
}

// ---------------- activations ----------------
__device__ __forceinline__ float actf(float x) {
    float s1 = fmaxf(x - 0.1f, 0.f) - fmaxf(-x - 0.1f, 0.f);
    float s2 = fmaxf(x - 0.5f, 0.f) - fmaxf(-x - 0.5f, 0.f);
    return 1.8f * s1 - 0.8f * s2;
}

__device__ __forceinline__ void store_split4(bf16* __restrict__ hi, bf16* __restrict__ lo,
                                             size_t idx2, float a, float b, float c, float d) {
    __nv_bfloat162 h01 = __floats2bfloat162_rn(a, b);
    __nv_bfloat162 h23 = __floats2bfloat162_rn(c, d);
    float lx = a - __bfloat162float(h01.x);
    float ly = b - __bfloat162float(h01.y);
    float lz = c - __bfloat162float(h23.x);
    float lw = d - __bfloat162float(h23.y);
    ((__nv_bfloat162*)hi)[idx2] = h01;
    ((__nv_bfloat162*)hi)[idx2 + 1] = h23;
    ((__nv_bfloat162*)lo)[idx2] = __floats2bfloat162_rn(lx, ly);
    ((__nv_bfloat162*)lo)[idx2 + 1] = __floats2bfloat162_rn(lz, lw);
}

// ---------------- CSR SpMM: F4 variant (64-wide layers) ----------------
template <int F4>
__global__ __launch_bounds__(256, 8) void k_spmm_relu4(
        const int* __restrict__ rowptr, const int2* __restrict__ edge,
        const float* __restrict__ X,
        const float* __restrict__ bias, float* __restrict__ outF,
        bf16* __restrict__ outHi, bf16* __restrict__ outLo) {
    int t = blockIdx.x * blockDim.x + threadIdx.x;
    int row = t / F4;
    int f = t % F4;
    if (row >= NNODES) return;
    int s = rowptr[row], e = rowptr[row + 1];
    const float4* X4 = (const float4*)X;
    float4 acc = make_float4(0.f, 0.f, 0.f, 0.f);
    for (int p = s; p < e; p++) {
        int2 ev = __ldg(&edge[p]);
        float v = __int_as_float(ev.y);
        float4 xv = X4[(size_t)ev.x * F4 + f];
        acc.x = fmaf(v, xv.x, acc.x);
        acc.y = fmaf(v, xv.y, acc.y);
        acc.z = fmaf(v, xv.z, acc.z);
        acc.w = fmaf(v, xv.w, acc.w);
    }
    float4 b = ((const float4*)bias)[f];
    float ox = fmaxf(acc.x + b.x, 0.f);
    float oy = fmaxf(acc.y + b.y, 0.f);
    float oz = fmaxf(acc.z + b.z, 0.f);
    float ow = fmaxf(acc.w + b.w, 0.f);
    ((float4*)outF)[(size_t)row * F4 + f] = make_float4(ox, oy, oz, ow);
    store_split4(outHi, outLo, ((size_t)row * F4 + f) * 2, ox, oy, oz, ow);
}

template <int F4>
__global__ __launch_bounds__(256, 8) void k_spmm_embed4(
        const int* __restrict__ rowptr, const int2* __restrict__ edge,
        const float* __restrict__ X,
        const float* __restrict__ T,
        bf16* __restrict__ outHi, bf16* __restrict__ outLo) {
    int t = blockIdx.x * blockDim.x + threadIdx.x;
    int row = t / F4;
    int f = t % F4;
    if (row >= NNODES) return;
    int s = rowptr[row], e = rowptr[row + 1];
    const float4* X4 = (const float4*)X;
    float4 acc = make_float4(0.f, 0.f, 0.f, 0.f);
    for (int p = s; p < e; p++) {
        int2 ev = __ldg(&edge[p]);
        float v = __int_as_float(ev.y);
        float4 xv = X4[(size_t)ev.x * F4 + f];
        acc.x = fmaf(v, xv.x, acc.x);
        acc.y = fmaf(v, xv.y, acc.y);
        acc.z = fmaf(v, xv.z, acc.z);
        acc.w = fmaf(v, xv.w, acc.w);
    }
    float4 tv = ((const float4*)T)[(size_t)row * F4 + f];
    float ox = actf(tv.x - acc.x);
    float oy = actf(tv.y - acc.y);
    float oz = actf(tv.z - acc.z);
    float ow = actf(tv.w - acc.w);
    store_split4(outHi, outLo, ((size_t)row * F4 + f) * 2, ox, oy, oz, ow);
}

// ---------------- CSR SpMM: F8 variant (256-wide layers; one warp per row) ----------------
template <int F8>
__global__ __launch_bounds__(256, 6) void k_spmm_relu8(
        const int* __restrict__ rowptr, const int2* __restrict__ edge,
        const float* __restrict__ X,
        const float* __restrict__ bias, float* __restrict__ outF,
        bf16* __restrict__ outHi, bf16* __restrict__ outLo) {
    int t = blockIdx.x * blockDim.x + threadIdx.x;
    int row = t / F8;
    int f = t % F8;             // unit of 8 floats = 2 float4
    if (row >= NNODES) return;
    int s = rowptr[row], e = rowptr[row + 1];
    const float4* X4 = (const float4*)X;
    float4 acc0 = make_float4(0.f, 0.f, 0.f, 0.f);
    float4 acc1 = make_float4(0.f, 0.f, 0.f, 0.f);
    for (int p = s; p < e; p++) {
        int2 ev = __ldg(&edge[p]);
        float v = __int_as_float(ev.y);
        size_t base = (size_t)ev.x * (F8 * 2) + f * 2;
        float4 x0 = X4[base];
        float4 x1 = X4[base + 1];
        acc0.x = fmaf(v, x0.x, acc0.x); acc0.y = fmaf(v, x0.y, acc0.y);
        acc0.z = fmaf(v, x0.z, acc0.z); acc0.w = fmaf(v, x0.w, acc0.w);
        acc1.x = fmaf(v, x1.x, acc1.x); acc1.y = fmaf(v, x1.y, acc1.y);
        acc1.z = fmaf(v, x1.z, acc1.z); acc1.w = fmaf(v, x1.w, acc1.w);
    }
    float4 b0 = ((const float4*)bias)[f * 2];
    float4 b1 = ((const float4*)bias)[f * 2 + 1];
    float o0x = fmaxf(acc0.x + b0.x, 0.f), o0y = fmaxf(acc0.y + b0.y, 0.f);
    float o0z = fmaxf(acc0.z + b0.z, 0.f), o0w = fmaxf(acc0.w + b0.w, 0.f);
    float o1x = fmaxf(acc1.x + b1.x, 0.f), o1y = fmaxf(acc1.y + b1.y, 0.f);
    float o1z = fmaxf(acc1.z + b1.z, 0.f), o1w = fmaxf(acc1.w + b1.w, 0.f);
    size_t o4 = (size_t)row * (F8 * 2) + f * 2;
    ((float4*)outF)[o4] = make_float4(o0x, o0y, o0z, o0w);
    ((float4*)outF)[o4 + 1] = make_float4(o1x, o1y, o1z, o1w);
    store_split4(outHi, outLo, o4 * 2, o0x, o0y, o0z, o0w);
    store_split4(outHi, outLo, o4 * 2 + 2, o1x, o1y, o1z, o1w);
}

template <int F8>
__global__ __launch_bounds__(256, 6) void k_spmm_embed8(
        const int* __restrict__ rowptr, const int2* __restrict__ edge,
        const float* __restrict__ X,
        const float* __restrict__ T,
        bf16* __restrict__ outHi, bf16* __restrict__ outLo) {
    int t = blockIdx.x * blockDim.x + threadIdx.x;
    int row = t / F8;
    int f = t % F8;
    if (row >= NNODES) return;
    int s = rowptr[row], e = rowptr[row + 1];
    const float4* X4 = (const float4*)X;
    float4 acc0 = make_float4(0.f, 0.f, 0.f, 0.f);
    float4 acc1 = make_float4(0.f, 0.f, 0.f, 0.f);
    for (int p = s; p < e; p++) {
        int2 ev = __ldg(&edge[p]);
        float v = __int_as_float(ev.y);
        size_t base = (size_t)ev.x * (F8 * 2) + f * 2;
        float4 x0 = X4[base];
        float4 x1 = X4[base + 1];
        acc0.x = fmaf(v, x0.x, acc0.x); acc0.y = fmaf(v, x0.y, acc0.y);
        acc0.z = fmaf(v, x0.z, acc0.z); acc0.w = fmaf(v, x0.w, acc0.w);
        acc1.x = fmaf(v, x1.x, acc1.x); acc1.y = fmaf(v, x1.y, acc1.y);
        acc1.z = fmaf(v, x1.z, acc1.z); acc1.w = fmaf(v, x1.w, acc1.w);
    }
    size_t o4 = (size_t)row * (F8 * 2) + f * 2;
    float4 t0 = ((const float4*)T)[o4];
    float4 t1 = ((const float4*)T)[o4 + 1];
    float o0x = actf(t0.x - acc0.x), o0y = actf(t0.y - acc0.y);
    float o0z = actf(t0.z - acc0.z), o0w = actf(t0.w - acc0.w);
    float o1x = actf(t1.x - acc1.x), o1y = actf(t1.y - acc1.y);
    float o1z = actf(t1.z - acc1.z), o1w = actf(t1.w - acc1.w);
    store_split4(outHi, outLo, o4 * 2, o0x, o0y, o0z, o0w);
    store_split4(outHi, outLo, o4 * 2 + 2, o1x, o1y, o1z, o1w);
}

// ---------------- tensor-core GEMM (pre-split bf16x3, cp.async + ldmatrix) ----------------
// Block-uniform split epilogue: split % 64 == 0 at every call site and BN = 64,
// so each block tile lies entirely in one output segment. Segment choice (pointer,
// stride, tanh) is made once per block. No reg cap: footprint matches plain epilogue.
__device__ __forceinline__ uint32_t s2u(const void* p) {
    return (uint32_t)__cvta_generic_to_shared(p);
}
__device__ __forceinline__ int aoff(int row, int k) {
    return row * 64 + (((k >> 3) ^ ((row >> 1) & 3)) << 4) + ((k & 7) << 1);
}
__device__ __forceinline__ int boff(int kr, int n) {
    return kr * 128 + (((n >> 3) ^ (kr & 7)) << 4) + ((n & 7) << 1);
}
__device__ __forceinline__ void cp16(uint32_t dst, const void* src) {
    asm volatile("cp.async.cg.shared.global [%0], [%1], 16;\n" ::"r"(dst), "l"(src));
}
__device__ __forceinline__ void ldm_x4(uint32_t addr, uint32_t& r0, uint32_t& r1,
                                       uint32_t& r2, uint32_t& r3) {
    asm volatile("ldmatrix.sync.aligned.m8n8.x4.shared.b16 {%0,%1,%2,%3}, [%4];\n"
                 : "=r"(r0), "=r"(r1), "=r"(r2), "=r"(r3) : "r"(addr));
}
__device__ __forceinline__ void ldm_x4t(uint32_t addr, uint32_t& r0, uint32_t& r1,
                                        uint32_t& r2, uint32_t& r3) {
    asm volatile("ldmatrix.sync.aligned.m8n8.x4.trans.shared.b16 {%0,%1,%2,%3}, [%4];\n"
                 : "=r"(r0), "=r"(r1), "=r"(r2), "=r"(r3) : "r"(addr));
}
__device__ __forceinline__ void mma_bf16(float& d0, float& d1, float& d2, float& d3,
                                         uint32_t a0, uint32_t a1, uint32_t a2, uint32_t a3,
                                         uint32_t b0, uint32_t b1) {
    asm volatile(
        "mma.sync.aligned.m16n8k16.row.col.f32.bf16.bf16.f32 "
        "{%0,%1,%2,%3}, {%4,%5,%6,%7}, {%8,%9}, {%0,%1,%2,%3};"
        : "+f"(d0), "+f"(d1), "+f"(d2), "+f"(d3)
        : "r"(a0), "r"(a1), "r"(a2), "r"(a3), "r"(b0), "r"(b1));
}

__global__ __launch_bounds__(256) void k_gemm_tc(
    const bf16* __restrict__ A1hi, const bf16* __restrict__ A1lo, int K1,
    const bf16* __restrict__ B1hi, const bf16* __restrict__ B1lo,
    const bf16* __restrict__ A2hi, const bf16* __restrict__ A2lo, int K2,
    const bf16* __restrict__ B2hi, const bf16* __restrict__ B2lo,
    int M, int Nc,
    float* __restrict__ C1, const float* __restrict__ bias1, int split,
    float* __restrict__ C2)
{
    __shared__ __align__(16) bf16 sA[2][2][128 * 32];
    __shared__ __align__(16) bf16 sB[2][2][32 * 64];

    int tid = threadIdx.x;
    int warp = tid >> 5, lane = tid & 31;
    int wm = warp & 3;
    int wn = warp >> 2;
    int bn = blockIdx.x * 64;
    int bm = blockIdx.y * 128;

    float acc[2][4][4];
#pragma unroll
    for (int i = 0; i < 2; i++)
#pragma unroll
        for (int j = 0; j < 4; j++)
#pragma unroll
            for (int c = 0; c < 4; c++) acc[i][j][c] = 0.f;

    const int T = (K1 + K2) / 32;

    int arow0 = tid >> 2, ac0 = tid & 3;
    int arow1 = (tid + 256) >> 2, ac1 = tid & 3;
    int garow0 = bm + arow0; if (garow0 >= M) garow0 = M - 1;
    int garow1 = bm + arow1; if (garow1 >= M) garow1 = M - 1;
    int bkr = tid >> 3, bc = tid & 7;

    auto loadTile = [&](int t, int stage) {
        int k0 = t * 32;
        const bf16 *Ahi, *Alo, *Bhi, *Blo;
        int kloc, K;
        if (k0 < K1) { Ahi = A1hi; Alo = A1lo; Bhi = B1hi; Blo = B1lo; kloc = k0; K = K1; }
        else         { Ahi = A2hi; Alo = A2lo; Bhi = B2hi; Blo = B2lo; kloc = k0 - K1; K = K2; }
        uint32_t sa_hi = s2u(&sA[stage][0][0]);
        uint32_t sa_lo = s2u(&sA[stage][1][0]);
        uint32_t sb_hi = s2u(&sB[stage][0][0]);
        uint32_t sb_lo = s2u(&sB[stage][1][0]);
        int so0 = aoff(arow0, ac0 * 8);
        int so1 = aoff(arow1, ac1 * 8);
        size_t g0 = (size_t)garow0 * K + kloc + ac0 * 8;
        size_t g1 = (size_t)garow1 * K + kloc + ac1 * 8;
        cp16(sa_hi + so0, Ahi + g0);
        cp16(sa_hi + so1, Ahi + g1);
        cp16(sa_lo + so0, Alo + g0);
        cp16(sa_lo + so1, Alo + g1);
        int sob = boff(bkr, bc * 8);
        size_t gb = (size_t)(kloc + bkr) * Nc + bn + bc * 8;
        cp16(sb_hi + sob, Bhi + gb);
        cp16(sb_lo + sob, Blo + gb);
        asm volatile("cp.async.commit_group;\n");
    };

    loadTile(0, 0);

    int a_r = (lane & 7) + ((lane & 8) ? 8 : 0);
    int a_k = (lane & 16) ? 8 : 0;
    int b_k = (lane & 7) + ((lane & 8) ? 8 : 0);
    int b_n = (lane & 16) ? 8 : 0;

    for (int t = 0; t < T; t++) {
        int s = t & 1;
        if (t + 1 < T) {
            loadTile(t + 1, (t + 1) & 1);
            asm volatile("cp.async.wait_group 1;\n");
        } else {
            asm volatile("cp.async.wait_group 0;\n");
        }
        __syncthreads();

        uint32_t sa_hi = s2u(&sA[s][0][0]);
        uint32_t sa_lo = s2u(&sA[s][1][0]);
        uint32_t sb_hi = s2u(&sB[s][0][0]);
        uint32_t sb_lo = s2u(&sB[s][1][0]);

#pragma unroll
        for (int ks = 0; ks < 32; ks += 16) {
            uint32_t ahi[2][4], alo[2][4], bhi[4][2], blo[4][2];
#pragma unroll
            for (int mf = 0; mf < 2; mf++) {
                int row = wm * 32 + mf * 16 + a_r;
                int off = aoff(row, ks + a_k);
                ldm_x4(sa_hi + off, ahi[mf][0], ahi[mf][1], ahi[mf][2], ahi[mf][3]);
                ldm_x4(sa_lo + off, alo[mf][0], alo[mf][1], alo[mf][2], alo[mf][3]);
            }
#pragma unroll
            for (int p = 0; p < 2; p++) {
                int kr = ks + b_k;
                int n = wn * 32 + p * 16 + b_n;
                int off = boff(kr, n);
                ldm_x4t(sb_hi + off, bhi[2 * p][0], bhi[2 * p][1], bhi[2 * p + 1][0], bhi[2 * p + 1][1]);
                ldm_x4t(sb_lo + off, blo[2 * p][0], blo[2 * p][1], blo[2 * p + 1][0], blo[2 * p + 1][1]);
            }
#pragma unroll
            for (int mf = 0; mf < 2; mf++)
#pragma unroll
                for (int nf = 0; nf < 4; nf++) {
                    float* d = acc[mf][nf];
                    mma_bf16(d[0], d[1], d[2], d[3],
                             ahi[mf][0], ahi[mf][1], ahi[mf][2], ahi[mf][3],
                             bhi[nf][0], bhi[nf][1]);
                    mma_bf16(d[0], d[1], d[2], d[3],
                             ahi[mf][0], ahi[mf][1], ahi[mf][2], ahi[mf][3],
                             blo[nf][0], blo[nf][1]);
                    mma_bf16(d[0], d[1], d[2], d[3],
                             alo[mf][0], alo[mf][1], alo[mf][2], alo[mf][3],
                             bhi[nf][0], bhi[nf][1]);
                }
        }
        __syncthreads();
    }

    // ---- block-uniform split epilogue ----
    bool seg1 = (bn < split);
    float* Cout = seg1 ? C1 : C2;
    int stride = seg1 ? split : (Nc - split);
    int colbase = seg1 ? bn : (bn - split);

#pragma unroll
    for (int mf = 0; mf < 2; mf++) {
        int row0 = bm + wm * 32 + mf * 16 + (lane >> 2);
#pragma unroll
        for (int nf = 0; nf < 4; nf++) {
            int col = colbase + wn * 32 + nf * 8 + (lane & 3) * 2;
            float* d = acc[mf][nf];
            float c0 = d[0], c1 = d[1], c2 = d[2], c3 = d[3];
            if (seg1) {
                float b0 = bias1[col], b1 = bias1[col + 1];
                c0 = tanhf(c0 + b0); c1 = tanhf(c1 + b1);
                c2 = tanhf(c2 + b0); c3 = tanhf(c3 + b1);
            }
            if (row0 < M) *(float2*)(Cout + (size_t)row0 * stride + col) = make_float2(c0, c1);
            if (row0 + 8 < M) *(float2*)(Cout + (size_t)(row0 + 8) * stride + col) = make_float2(c2, c3);
        }
    }
}

// ---------------- host orchestration ----------------
static inline void gemm(const bf16* A1h, const bf16* A1l, int K1, const bf16* B1h, const bf16* B1l,
                        const bf16* A2h, const bf16* A2l, int K2, const bf16* B2h, const bf16* B2l,
                        int M, int Nc, float* C1, const float* bias1, int split, float* C2) {
    dim3 grid(Nc / 64, (M + 127) / 128);
    k_gemm_tc<<<grid, 256>>>(A1h, A1l, K1, B1h, B1l, A2h, A2l, K2, B2h, B2l,
                             M, Nc, C1, bias1, split, C2);
}

extern "C" void kernel_launch(void* const* d_in, const int* in_sizes, int n_in,
                              void* d_out, int out_size) {
    (void)in_sizes; (void)n_in; (void)out_size;
    const float* x      = (const float*)d_in[0];
    const int*   A_idx  = (const int*)d_in[1];
    const float* A_val  = (const float*)d_in[2];
    const int*   L_idx  = (const int*)d_in[3];
    const float* L_val  = (const float*)d_in[4];
    const float* gcn_w0 = (const float*)d_in[5];
    const float* gcn_b0 = (const float*)d_in[6];
    const float* pai1_0 = (const float*)d_in[7];
    const float* pai2_0 = (const float*)d_in[8];
    const float* w1_w0  = (const float*)d_in[9];
    const float* w1_b0  = (const float*)d_in[10];
    const float* w2_w0  = (const float*)d_in[11];
    const float* w2_b0  = (const float*)d_in[12];
    const float* gcn_w1 = (const float*)d_in[13];
    const float* gcn_b1 = (const float*)d_in[14];
    const float* pai1_1 = (const float*)d_in[15];
    const float* pai2_1 = (const float*)d_in[16];
    const float* w1_w1  = (const float*)d_in[17];
    const float* w1_b1  = (const float*)d_in[18];
    const float* w2_w1  = (const float*)d_in[19];
    const float* w2_b1  = (const float*)d_in[20];

    float* out = (float*)d_out;
    float* out_ztp0 = out;
    float* out_ztp1 = out + (size_t)NNODES * FOUT;
    float* out_zem0 = out + (size_t)2 * NNODES * FOUT;
    float* out_zem1 = out + (size_t)3 * NNODES * FOUT;

    float *buf0, *buf1, *buf2;
    bf16 *xhi, *xlo, *zhi, *zlo, *whi, *wlo, *wb1hi, *wb1lo;
    int *rowptrA, *rowptrL, *cntA, *cntL;
    int2 *edgeA, *edgeL;
    cudaGetSymbolAddress((void**)&buf0, g_buf0);
    cudaGetSymbolAddress((void**)&buf1, g_buf1);
    cudaGetSymbolAddress((void**)&buf2, g_buf2);
    cudaGetSymbolAddress((void**)&xhi, g_xhi);
    cudaGetSymbolAddress((void**)&xlo, g_xlo);
    cudaGetSymbolAddress((void**)&zhi, g_zhi);
    cudaGetSymbolAddress((void**)&zlo, g_zlo);
    cudaGetSymbolAddress((void**)&whi, g_whi);
    cudaGetSymbolAddress((void**)&wlo, g_wlo);
    cudaGetSymbolAddress((void**)&wb1hi, g_wb1hi);
    cudaGetSymbolAddress((void**)&wb1lo, g_wb1lo);
    cudaGetSymbolAddress((void**)&rowptrA, g_rowptrA);
    cudaGetSymbolAddress((void**)&edgeA, g_edgeA);
    cudaGetSymbolAddress((void**)&rowptrL, g_rowptrL);
    cudaGetSymbolAddress((void**)&edgeL, g_edgeL);
    cudaGetSymbolAddress((void**)&cntA, g_cntA);
    cudaGetSymbolAddress((void**)&cntL, g_cntL);

    const int TB = 256;
    int gbN = (NNODES + TB - 1) / TB;
    int gbE = (NEDGES + TB - 1) / TB;
    int nChunks = (NNODES + 1023) / 1024;

    // ---- splits first, then CSR count/scan, GEMM0 at slot 6 ----
    {
        int n4 = NNODES * FDIN / 4;
        k_split<<<(n4 + TB - 1) / TB, TB>>>(x, xhi, xlo, n4);                 // 1
        WSplit ws;
        ws.src[0] = gcn_w0; ws.n4[0] = 65536 / 4; ws.off[0] = OFF_GCN_W0;
        ws.src[1] = pai1_0; ws.n4[1] = 65536 / 4; ws.off[1] = OFF_PAI1_0;
        ws.src[2] = pai2_0; ws.n4[2] = 65536 / 4; ws.off[2] = OFF_PAI2_0;
        ws.src[3] = w1_w0;  ws.n4[3] = 16384 / 4; ws.off[3] = OFF_W1_W0;
        ws.src[4] = w2_w0;  ws.n4[4] = 16384 / 4; ws.off[4] = OFF_W2_W0;
        ws.src[5] = gcn_w1; ws.n4[5] = 16384 / 4; ws.off[5] = OFF_GCN_W1;
        ws.src[6] = pai1_1; ws.n4[6] = 4096 / 4;  ws.off[6] = OFF_PAI1_1;
        ws.src[7] = pai2_1; ws.n4[7] = 16384 / 4; ws.off[7] = OFF_PAI2_1;
        ws.src[8] = w1_w1;  ws.n4[8] = 4096 / 4;  ws.off[8] = OFF_W1_W1;
        ws.src[9] = w2_w1;  ws.n4[9] = 4096 / 4;  ws.off[9] = OFF_W2_W1;
        dim3 grid(64, 10);
        k_split_weights<<<grid, TB>>>(ws, whi, wlo);                          // 2
        k_build_wb1<<<(256 * 128 + TB - 1) / TB, TB>>>(w2_w0, gcn_w1, wb1hi, wb1lo); // 3
    }
    k_zero2<<<gbN, TB>>>(cntA, cntL, NNODES);                                 // 4
    {
        dim3 g(gbE, 2);
        k_count2<<<g, TB>>>(A_idx, L_idx, cntA, cntL, NEDGES);                // 5
    }
    // layer-0 GCN GEMM — slot 6 (ncu -s 5 profiles this)
    gemm(xhi, xlo, FDIN, whi + OFF_GCN_W0, wlo + OFF_GCN_W0,
         nullptr, nullptr, 0, nullptr, nullptr,
         NNODES, FH, nullptr, nullptr, 0, buf0);
    {
        dim3 g(nChunks, 2);
        k_scan_reduce2<<<g, 256>>>(cntA, cntL, NNODES);
        dim3 g1(1, 2);
        k_scan_part2<<<g1, 128>>>(nChunks);
        k_scan_final2<<<g, 256>>>(cntA, cntL, rowptrA, rowptrL, NNODES);
        dim3 ge(gbE, 2);
        // cnt arrays re-zeroed by scan_final -> reused as scatter cursors
        k_scatter2<<<ge, TB>>>(A_idx, A_val, L_idx, L_val, rowptrA, rowptrL,
                               cntA, cntL, edgeA, edgeL, NEDGES);
    }

    // ================= layer 0 (din=256 -> h=256) =================
    {
        int threads = NNODES * (FH / 8);
        k_spmm_relu8<FH / 8><<<(threads + TB - 1) / TB, TB>>>(rowptrA, edgeA, buf0,
                                                              gcn_b0, buf1, zhi, zlo);
    }
    // tanh(z@w1_w0 + b) -> out_ztp0   (all C1)
    gemm(zhi, zlo, FH, whi + OFF_W1_W0, wlo + OFF_W1_W0,
         nullptr, nullptr, 0, nullptr, nullptr,
         NNODES, 64, out_ztp0, w1_b0, 64, nullptr);
    // z@pai1_0 + x@pai2_0 -> buf2     (all C2)
    gemm(zhi, zlo, FH, whi + OFF_PAI1_0, wlo + OFF_PAI1_0,
         xhi, xlo, FDIN, whi + OFF_PAI2_0, wlo + OFF_PAI2_0,
         NNODES, 256, nullptr, nullptr, 0, buf2);
    {
        int threads = NNODES * (FH / 8);
        k_spmm_embed8<FH / 8><<<(threads + TB - 1) / TB, TB>>>(rowptrL, edgeL, buf1,
                                                               buf2, zhi, zlo);
    }
    // FUSED WB1: [tanh(zem0@w2_w0 + b) -> out_zem0 | zem0@gcn_w1 -> buf0], Nc=128
    gemm(zhi, zlo, FH, wb1hi, wb1lo,
         nullptr, nullptr, 0, nullptr, nullptr,
         NNODES, 128, out_zem0, w2_b0, 64, buf0);

    // ================= layer 1 (h=256 -> dout=64) =================
    {
        int threads = NNODES * (FOUT / 4);
        k_spmm_relu4<FOUT / 4><<<(threads + TB - 1) / TB, TB>>>(rowptrA, edgeA, buf0,
                                                                gcn_b1, buf1, zhi, zlo);
    }
    // tanh(z@w1_w1 + b) -> out_ztp1
    gemm(zhi, zlo, FOUT, whi + OFF_W1_W1, wlo + OFF_W1_W1,
         nullptr, nullptr, 0, nullptr, nullptr,
         NNODES, 64, out_ztp1, w1_b1, 64, nullptr);
    // z@pai1_1 + x@pai2_1 -> buf2
    gemm(zhi, zlo, FOUT, whi + OFF_PAI1_1, wlo + OFF_PAI1_1,
         xhi, xlo, FDIN, whi + OFF_PAI2_1, wlo + OFF_PAI2_1,
         NNODES, 64, nullptr, nullptr, 0, buf2);
    {
        int threads = NNODES * (FOUT / 4);
        k_spmm_embed4<FOUT / 4><<<(threads + TB - 1) / TB, TB>>>(rowptrL, edgeL, buf1,
                                                                 buf2, zhi, zlo);
    }
    // tanh(zem1@w2_w1 + b) -> out_zem1
    gemm(zhi, zlo, FOUT, whi + OFF_W2_W1, wlo + OFF_W2_W1,
         nullptr, nullptr, 0, nullptr, nullptr,
         NNODES, 64, out_zem1, w2_b1, 64, nullptr);
}